// round 1
// baseline (speedup 1.0000x reference)
#include <cuda_runtime.h>
#include <cuda_bf16.h>

// Welford running mean/variance over batch dim of x: (B, C, H, W), B=256, CHW=262144.
// Output layout (float32, concatenated, matching reference return order):
//   [0, B*CHW)                      : x passthrough
//   [B*CHW, B*CHW+CHW)              : m
//   [B*CHW+CHW, B*CHW+2*CHW)        : s
//   [B*CHW+2*CHW, B*CHW+3*CHW)      : neuron_nonzero (int -> float)
//   [B*CHW+3*CHW]                   : n_samples + B (int -> float)

__global__ void welford_kernel(const float* __restrict__ x,
                               const float* __restrict__ m_in,
                               const float* __restrict__ s_in,
                               const int*   __restrict__ nn_in,
                               const int*   __restrict__ n_in,
                               float* __restrict__ out,
                               int B, int CHW)
{
    int p = blockIdx.x * blockDim.x + threadIdx.x;
    if (p >= CHW) return;

    float m  = m_in[p];
    float s  = s_in[p];
    int   nn = nn_in[p];
    const int n0 = n_in[0];

    const float* xp = x + p;
    float*       op = out + p;

    #pragma unroll 8
    for (int b = 0; b < B; ++b) {
        float xv = xp[(size_t)b * CHW];
        op[(size_t)b * CHW] = xv;                 // passthrough of x

        nn += (xv != 0.0f) ? 1 : 0;
        float old_m = m;
        float inv = __fdividef(1.0f, (float)(n0 + b + 1));  // MUFU.RCP path
        m = m + (xv - m) * inv;
        s = s + (xv - m) * (xv - old_m);
    }

    size_t base = (size_t)B * (size_t)CHW;
    out[base + p]               = m;
    out[base + (size_t)CHW + p] = s;
    out[base + 2 * (size_t)CHW + p] = (float)nn;
    if (p == 0) {
        out[base + 3 * (size_t)CHW] = (float)(n0 + B);
    }
}

extern "C" void kernel_launch(void* const* d_in, const int* in_sizes, int n_in,
                              void* d_out, int out_size)
{
    const float* x  = (const float*)d_in[0];
    const float* m  = (const float*)d_in[1];
    const float* s  = (const float*)d_in[2];
    const int*   nn = (const int*)d_in[3];
    const int*   n  = (const int*)d_in[4];
    float* out = (float*)d_out;

    const int CHW = in_sizes[1];          // 262144
    const int B   = in_sizes[0] / CHW;    // 256

    const int threads = 256;
    const int blocks = (CHW + threads - 1) / threads;  // 1024
    welford_kernel<<<blocks, threads>>>(x, m, s, nn, n, out, B, CHW);
}